// round 8
// baseline (speedup 1.0000x reference)
#include <cuda_runtime.h>
#include <cuda_bf16.h>
#include <cstdint>
#include <math.h>

#define TLEN   2048
#define FDIM   256
#define NHEAD  8
#define NBATCH 4
#define NBH    32

typedef __nv_bfloat16 bf16;

// ---------------- scratch (__device__ globals; no allocation allowed) ----------------
__device__ __align__(16) bf16 g_xh [(size_t)NBATCH * TLEN * FDIM];
__device__ __align__(16) bf16 g_xl [(size_t)NBATCH * TLEN * FDIM];
__device__ __align__(16) bf16 g_Wqh[(size_t)(NHEAD * FDIM * 3) * FDIM];   // WqkvT hi [6144][256]
__device__ __align__(16) bf16 g_Wql[(size_t)(NHEAD * FDIM * 3) * FDIM];
__device__ __align__(16) bf16 g_Wph[(size_t)FDIM * (NHEAD * FDIM)];       // WprojT hi [256][2048]
__device__ __align__(16) bf16 g_Wpl[(size_t)FDIM * (NHEAD * FDIM)];
__device__ __align__(16) bf16 g_Qh [(size_t)NBH * TLEN * FDIM];           // [bh][t][f]
__device__ __align__(16) bf16 g_Ql [(size_t)NBH * TLEN * FDIM];
__device__ __align__(16) bf16 g_Kh [(size_t)NBH * TLEN * FDIM];
__device__ __align__(16) bf16 g_Kl [(size_t)NBH * TLEN * FDIM];
__device__ __align__(16) bf16 g_Vth[(size_t)NBH * FDIM * TLEN];           // [bh][f][t]
__device__ __align__(16) bf16 g_Vtl[(size_t)NBH * FDIM * TLEN];
__device__ __align__(16) float g_S [(size_t)NBH * TLEN * TLEN];           // fp32 scores
__device__ __align__(16) bf16 g_Ph [(size_t)NBH * TLEN * TLEN];           // probs hi
__device__ __align__(16) bf16 g_Pl [(size_t)NBH * TLEN * TLEN];           // probs lo
__device__ __align__(16) bf16 g_ah [(size_t)NBATCH * TLEN * NHEAD * FDIM];// attn hi [b][t][h*f]
__device__ __align__(16) bf16 g_al [(size_t)NBATCH * TLEN * NHEAD * FDIM];

// ---------------- helpers ----------------
__device__ __forceinline__ uint32_t smem_u32(const void* p) {
    uint32_t a;
    asm("{ .reg .u64 t; cvta.to.shared.u64 t, %1; cvt.u32.u64 %0, t; }" : "=r"(a) : "l"(p));
    return a;
}
__device__ __forceinline__ void cp_async16(uint32_t dst, const void* src) {
    asm volatile("cp.async.cg.shared.global [%0], [%1], 16;" :: "r"(dst), "l"(src) : "memory");
}
__device__ __forceinline__ void cp_commit() {
    asm volatile("cp.async.commit_group;" ::: "memory");
}
template<int N> __device__ __forceinline__ void cp_wait() {
    asm volatile("cp.async.wait_group %0;" :: "n"(N) : "memory");
}
__device__ __forceinline__ void mma_bf16(float* c, const uint32_t* a, const uint32_t* b) {
    asm volatile(
        "mma.sync.aligned.m16n8k16.row.col.f32.bf16.bf16.f32 "
        "{%0,%1,%2,%3}, {%4,%5,%6,%7}, {%8,%9}, {%0,%1,%2,%3};"
        : "+f"(c[0]), "+f"(c[1]), "+f"(c[2]), "+f"(c[3])
        : "r"(a[0]), "r"(a[1]), "r"(a[2]), "r"(a[3]), "r"(b[0]), "r"(b[1]));
}
// split fp32 pair -> packed bf16x2 hi + bf16x2 lo residual (.x in low half)
__device__ __forceinline__ void split_pair(float2 f, uint32_t& hi, uint32_t& lo) {
    uint32_t h;
    asm("cvt.rn.bf16x2.f32 %0, %1, %2;" : "=r"(h) : "f"(f.y), "f"(f.x));
    const float h0 = __uint_as_float(h << 16);
    const float h1 = __uint_as_float(h & 0xffff0000u);
    asm("cvt.rn.bf16x2.f32 %0, %1, %2;" : "=r"(lo) : "f"(f.y - h1), "f"(f.x - h0));
    hi = h;
}
__device__ __forceinline__ void split1(float v, bf16& h, bf16& l) {
    h = __float2bfloat16(v);
    l = __float2bfloat16(v - __bfloat162float(h));
}

// ---------------- GEMM config ----------------
constexpr int BM = 128, BN = 128, BK = 32;
constexpr int SROWW = 20;                              // words per row (16 data + 4 pad); conflict-free
constexpr int TILE_WORDS  = BM * SROWW;                // 2560
constexpr int STAGE_WORDS = 4 * TILE_WORDS;            // Ah, Al, Bh, Bl
constexpr int STAGE_BYTES = STAGE_WORDS * 4;           // 40960
constexpr int SMEM_NEED   = 2 * STAGE_BYTES;           // 81920

// MODE 0: C[8192,6144] = x @ WqkvT^T    (K=256)  -> scatter split Q/K/Vt (+bias, *1/16)
// MODE 1: C[2048,2048] = Q_bh @ K_bh^T  (K=256)  -> g_S (fp32)
// MODE 2: C[2048, 256] = P_bh @ Vt_bh^T (K=2048) -> split g_ah/g_al [B,T,H*F]
// MODE 3: C[8192, 256] = attn @ WprojT^T(K=2048) -> d_out fp32 (+bias)
template<int MODE>
__global__ void __launch_bounds__(256, 2)
mma_gemm(const float* __restrict__ bias, float* __restrict__ Cgp)
{
    constexpr int K  = (MODE == 0 || MODE == 1) ? 256 : 2048;
    constexpr int KT = K / BK;

    extern __shared__ uint32_t smem_w[];
    const uint32_t sbase = smem_u32(smem_w);

    const int tid = threadIdx.x;
    const int wid = tid >> 5, lid = tid & 31;
    const int z = blockIdx.z;
    const int rowBase = blockIdx.y * BM;
    const int colBase = blockIdx.x * BN;

    const bf16 *Ah, *Al, *Bh, *Bl;
    if (MODE == 0) {
        Ah = g_xh;  Al = g_xl;  Bh = g_Wqh; Bl = g_Wql;
    } else if (MODE == 1) {
        const size_t o = (size_t)z * TLEN * FDIM;
        Ah = g_Qh + o; Al = g_Ql + o; Bh = g_Kh + o; Bl = g_Kl + o;
    } else if (MODE == 2) {
        const size_t oa = (size_t)z * TLEN * TLEN;
        const size_t ob = (size_t)z * FDIM * TLEN;
        Ah = g_Ph + oa; Al = g_Pl + oa; Bh = g_Vth + ob; Bl = g_Vtl + ob;
    } else {
        Ah = g_ah;  Al = g_al;  Bh = g_Wph; Bl = g_Wpl;
    }
    Ah += (size_t)rowBase * K; Al += (size_t)rowBase * K;
    Bh += (size_t)colBase * K; Bl += (size_t)colBase * K;

    // loader: per tile 512 chunks of 16B (8 bf16); 4 tiles; 256 threads x 8 chunks
    auto load_tile = [&](int kt, int s) {
        const uint32_t base = sbase + s * STAGE_BYTES;
        const int kofs = kt * BK;
        #pragma unroll
        for (int i = 0; i < 2; ++i) {
            const int f   = tid + 256 * i;
            const int row = f >> 2;
            const int c16 = f & 3;
            const uint32_t so = (uint32_t)(row * SROWW + c16 * 4) * 4;
            const size_t go = (size_t)row * K + kofs + c16 * 8;
            cp_async16(base + 0 * TILE_WORDS * 4 + so, Ah + go);
            cp_async16(base + 1 * TILE_WORDS * 4 + so, Al + go);
            cp_async16(base + 2 * TILE_WORDS * 4 + so, Bh + go);
            cp_async16(base + 3 * TILE_WORDS * 4 + so, Bl + go);
        }
        cp_commit();
    };

    const int warp_m = wid & 3;   // 4 warps x 32 rows
    const int warp_n = wid >> 2;  // 2 warps x 64 cols
    const int gid = lid >> 2;     // 0..7
    const int tig = lid & 3;      // 0..3

    float acc[2][8][4];
    #pragma unroll
    for (int i = 0; i < 2; ++i)
        #pragma unroll
        for (int j = 0; j < 8; ++j)
            #pragma unroll
            for (int c = 0; c < 4; ++c) acc[i][j][c] = 0.f;

    load_tile(0, 0);

    #pragma unroll 1
    for (int kt = 0; kt < KT; ++kt) {
        const int s = kt & 1;
        if (kt + 1 < KT) { load_tile(kt + 1, s ^ 1); cp_wait<1>(); }
        else             { cp_wait<0>(); }
        __syncthreads();

        const uint32_t* st   = smem_w + s * STAGE_WORDS;
        const uint32_t* Ah_s = st + 0 * TILE_WORDS + (32 * warp_m) * SROWW;
        const uint32_t* Al_s = st + 1 * TILE_WORDS + (32 * warp_m) * SROWW;
        const uint32_t* Bh_s = st + 2 * TILE_WORDS + (64 * warp_n) * SROWW;
        const uint32_t* Bl_s = st + 3 * TILE_WORDS + (64 * warp_n) * SROWW;

        #pragma unroll
        for (int ks = 0; ks < 2; ++ks) {             // two m16n8k16 K-steps per BK=32
            const int kp = ks * 8 + tig;             // bf16x2 word index along K

            uint32_t ah[2][4], al[2][4];
            #pragma unroll
            for (int i = 0; i < 2; ++i) {
                const uint32_t* p = Ah_s + (16 * i + gid) * SROWW + kp;
                ah[i][0] = p[0]; ah[i][1] = p[8 * SROWW]; ah[i][2] = p[4]; ah[i][3] = p[8 * SROWW + 4];
                const uint32_t* q = Al_s + (16 * i + gid) * SROWW + kp;
                al[i][0] = q[0]; al[i][1] = q[8 * SROWW]; al[i][2] = q[4]; al[i][3] = q[8 * SROWW + 4];
            }

            #pragma unroll
            for (int jh = 0; jh < 2; ++jh) {         // halves of 4 columns (reg pressure)
                uint32_t bh[4][2], bl[4][2];
                #pragma unroll
                for (int j = 0; j < 4; ++j) {
                    const uint32_t* p = Bh_s + (8 * (jh * 4 + j) + gid) * SROWW + kp;
                    bh[j][0] = p[0]; bh[j][1] = p[4];
                    const uint32_t* q = Bl_s + (8 * (jh * 4 + j) + gid) * SROWW + kp;
                    bl[j][0] = q[0]; bl[j][1] = q[4];
                }
                #pragma unroll
                for (int i = 0; i < 2; ++i)
                    #pragma unroll
                    for (int j = 0; j < 4; ++j) {
                        float* c = acc[i][jh * 4 + j];
                        mma_bf16(c, ah[i], bh[j]);   // hi*hi
                        mma_bf16(c, ah[i], bl[j]);   // hi*lo
                        mma_bf16(c, al[i], bh[j]);   // lo*hi
                    }
            }
        }
        __syncthreads();
    }

    // ---------------- epilogue ----------------
    const int gm = rowBase + 32 * warp_m;
    const int gn = colBase + 64 * warp_n + 2 * tig;

    #pragma unroll
    for (int i = 0; i < 2; ++i) {
        #pragma unroll
        for (int h = 0; h < 2; ++h) {
            const int m = gm + 16 * i + gid + 8 * h;

            if (MODE == 0) {
                const int b = m >> 11, t = m & (TLEN - 1);
                #pragma unroll
                for (int j = 0; j < 8; ++j) {
                    #pragma unroll
                    for (int c = 0; c < 2; ++c) {
                        const int jj = gn + 8 * j + c;
                        float v = acc[i][j][2 * h + c] + bias[jj];
                        const int hh = jj / (FDIM * 3);
                        const int rr = jj - hh * (FDIM * 3);
                        const int f  = rr / 3;
                        const int cc = rr - f * 3;
                        const size_t bh = (size_t)(b * NHEAD + hh);
                        bf16 vh, vl;
                        if (cc == 0) {
                            v *= 0.0625f; split1(v, vh, vl);
                            const size_t idx = (bh * TLEN + t) * FDIM + f;
                            g_Qh[idx] = vh; g_Ql[idx] = vl;
                        } else if (cc == 1) {
                            v *= 0.0625f; split1(v, vh, vl);
                            const size_t idx = (bh * TLEN + t) * FDIM + f;
                            g_Kh[idx] = vh; g_Kl[idx] = vl;
                        } else {
                            split1(v, vh, vl);
                            const size_t idx = (bh * FDIM + f) * TLEN + t;
                            g_Vth[idx] = vh; g_Vtl[idx] = vl;
                        }
                    }
                }
            } else if (MODE == 1) {
                float* p = g_S + (size_t)z * TLEN * TLEN + (size_t)m * TLEN + gn;
                #pragma unroll
                for (int j = 0; j < 8; ++j)
                    *(float2*)(p + 8 * j) = make_float2(acc[i][j][2 * h], acc[i][j][2 * h + 1]);
            } else if (MODE == 2) {
                const int b = z >> 3, hh = z & 7;
                const size_t base = ((size_t)(b * TLEN + m)) * (NHEAD * FDIM) + hh * FDIM + gn;
                #pragma unroll
                for (int j = 0; j < 8; ++j) {
                    uint32_t hw, lw;
                    split_pair(make_float2(acc[i][j][2 * h], acc[i][j][2 * h + 1]), hw, lw);
                    *(uint32_t*)(g_ah + base + 8 * j) = hw;
                    *(uint32_t*)(g_al + base + 8 * j) = lw;
                }
            } else {
                float* p = Cgp + (size_t)m * FDIM + gn;
                #pragma unroll
                for (int j = 0; j < 8; ++j)
                    *(float2*)(p + 8 * j) = make_float2(acc[i][j][2 * h]     + bias[gn + 8 * j],
                                                        acc[i][j][2 * h + 1] + bias[gn + 8 * j + 1]);
            }
        }
    }
}

// ---------------- input split: x -> g_xh/g_xl ----------------
__global__ void __launch_bounds__(256) split_x_kernel(const float* __restrict__ x)
{
    const size_t i = ((size_t)blockIdx.x * 256 + threadIdx.x) * 4;
    const float4 v = *(const float4*)(x + i);
    uint32_t h0, l0, h1, l1;
    split_pair(make_float2(v.x, v.y), h0, l0);
    split_pair(make_float2(v.z, v.w), h1, l1);
    *(uint32_t*)(g_xh + i)     = h0;
    *(uint32_t*)(g_xh + i + 2) = h1;
    *(uint32_t*)(g_xl + i)     = l0;
    *(uint32_t*)(g_xl + i + 2) = l1;
}

// ---------------- weight transpose + split ----------------
template<int W>
__global__ void __launch_bounds__(256) transpose_kernel(const float* __restrict__ in)
{
    constexpr int R = (W == 0) ? FDIM : (NHEAD * FDIM);   // input rows
    constexpr int C = (W == 0) ? (NHEAD * FDIM * 3) : FDIM;
    bf16* outh = (W == 0) ? g_Wqh : g_Wph;                // [C][R]
    bf16* outl = (W == 0) ? g_Wql : g_Wpl;

    __shared__ float t[32][33];
    const int cx = blockIdx.x * 32 + threadIdx.x;
    const int ry = blockIdx.y * 32 + threadIdx.y;
    #pragma unroll
    for (int i = 0; i < 32; i += 8)
        t[threadIdx.y + i][threadIdx.x] = in[(size_t)(ry + i) * C + cx];
    __syncthreads();
    const int oc = blockIdx.y * 32 + threadIdx.x;
    const int orow = blockIdx.x * 32 + threadIdx.y;
    #pragma unroll
    for (int i = 0; i < 32; i += 8) {
        bf16 vh, vl;
        split1(t[threadIdx.x][threadIdx.y + i], vh, vl);
        outh[(size_t)(orow + i) * R + oc] = vh;
        outl[(size_t)(orow + i) * R + oc] = vl;
    }
}

// ---------------- softmax: 65536 rows of 2048; write split bf16 probs ----------------
__global__ void __launch_bounds__(256) softmax_kernel()
{
    const size_t row = blockIdx.x;
    const float* p = g_S + row * (size_t)TLEN;
    const int t = threadIdx.x;

    float4 v0 = ((const float4*)p)[t];
    float4 v1 = ((const float4*)p)[t + 256];

    float m = fmaxf(fmaxf(fmaxf(v0.x, v0.y), fmaxf(v0.z, v0.w)),
                    fmaxf(fmaxf(v1.x, v1.y), fmaxf(v1.z, v1.w)));
    #pragma unroll
    for (int o = 16; o; o >>= 1) m = fmaxf(m, __shfl_xor_sync(0xffffffffu, m, o));

    __shared__ float red[8];
    const int warp = t >> 5, lane = t & 31;
    if (lane == 0) red[warp] = m;
    __syncthreads();
    float bm = red[0];
    #pragma unroll
    for (int i = 1; i < 8; ++i) bm = fmaxf(bm, red[i]);
    __syncthreads();

    v0.x = __expf(v0.x - bm); v0.y = __expf(v0.y - bm);
    v0.z = __expf(v0.z - bm); v0.w = __expf(v0.w - bm);
    v1.x = __expf(v1.x - bm); v1.y = __expf(v1.y - bm);
    v1.z = __expf(v1.z - bm); v1.w = __expf(v1.w - bm);

    float s = v0.x + v0.y + v0.z + v0.w + v1.x + v1.y + v1.z + v1.w;
    #pragma unroll
    for (int o = 16; o; o >>= 1) s += __shfl_xor_sync(0xffffffffu, s, o);
    if (lane == 0) red[warp] = s;
    __syncthreads();
    float bs = 0.f;
    #pragma unroll
    for (int i = 0; i < 8; ++i) bs += red[i];

    const float inv = 1.0f / bs;
    v0.x *= inv; v0.y *= inv; v0.z *= inv; v0.w *= inv;
    v1.x *= inv; v1.y *= inv; v1.z *= inv; v1.w *= inv;

    uint32_t* ph = (uint32_t*)(g_Ph + row * (size_t)TLEN);
    uint32_t* pl = (uint32_t*)(g_Pl + row * (size_t)TLEN);
    uint32_t hw, lw;
    split_pair(make_float2(v0.x, v0.y), hw, lw); ph[2 * t]       = hw; pl[2 * t]       = lw;
    split_pair(make_float2(v0.z, v0.w), hw, lw); ph[2 * t + 1]   = hw; pl[2 * t + 1]   = lw;
    split_pair(make_float2(v1.x, v1.y), hw, lw); ph[2 * t + 512] = hw; pl[2 * t + 512] = lw;
    split_pair(make_float2(v1.z, v1.w), hw, lw); ph[2 * t + 513] = hw; pl[2 * t + 513] = lw;
}

// ---------------- launch ----------------
extern "C" void kernel_launch(void* const* d_in, const int* in_sizes, int n_in,
                              void* d_out, int out_size)
{
    const float* x     = (const float*)d_in[0];
    const float* Wqkv  = (const float*)d_in[1];
    const float* bqkv  = (const float*)d_in[2];
    const float* Wproj = (const float*)d_in[3];
    const float* bproj = (const float*)d_in[4];
    float* out = (float*)d_out;

    cudaFuncSetAttribute(mma_gemm<0>, cudaFuncAttributeMaxDynamicSharedMemorySize, SMEM_NEED);
    cudaFuncSetAttribute(mma_gemm<1>, cudaFuncAttributeMaxDynamicSharedMemorySize, SMEM_NEED);
    cudaFuncSetAttribute(mma_gemm<2>, cudaFuncAttributeMaxDynamicSharedMemorySize, SMEM_NEED);
    cudaFuncSetAttribute(mma_gemm<3>, cudaFuncAttributeMaxDynamicSharedMemorySize, SMEM_NEED);

    // prep: split x; transpose+split weights
    split_x_kernel<<<(NBATCH * TLEN * FDIM) / 1024, 256>>>(x);
    transpose_kernel<0><<<dim3(6144 / 32, 256 / 32), dim3(32, 8)>>>(Wqkv);
    transpose_kernel<1><<<dim3(256 / 32, 2048 / 32), dim3(32, 8)>>>(Wproj);

    // 1) QKV GEMM (+bias, scale, scatter split Q/K/Vt)
    mma_gemm<0><<<dim3(6144 / BN, 8192 / BM, 1), 256, SMEM_NEED>>>(bqkv, nullptr);
    // 2) scores = Q K^T (batched over 32 bh) -> fp32 S
    mma_gemm<1><<<dim3(TLEN / BN, TLEN / BM, NBH), 256, SMEM_NEED>>>(nullptr, nullptr);
    // 3) softmax -> split bf16 P
    softmax_kernel<<<NBH * TLEN, 256>>>();
    // 4) out = P V (batched, NT against Vt) -> split bf16 attn
    mma_gemm<2><<<dim3(FDIM / BN, TLEN / BM, NBH), 256, SMEM_NEED>>>(nullptr, nullptr);
    // 5) proj (+bias) -> fp32 out
    mma_gemm<3><<<dim3(FDIM / BN, 8192 / BM, 1), 256, SMEM_NEED>>>(bproj, out);
}

// round 9
// speedup vs baseline: 1.3905x; 1.3905x over previous
#include <cuda_runtime.h>
#include <cuda_bf16.h>
#include <cstdint>
#include <math.h>

#define TLEN   2048
#define FDIM   256
#define NHEAD  8
#define NBATCH 4
#define NBH    32

typedef __nv_bfloat16 bf16;

// ---------------- scratch (__device__ globals; no allocation allowed) ----------------
__device__ __align__(16) bf16 g_xh [(size_t)NBATCH * TLEN * FDIM];
__device__ __align__(16) bf16 g_xl [(size_t)NBATCH * TLEN * FDIM];
__device__ __align__(16) bf16 g_Wqh[(size_t)(NHEAD * FDIM * 3) * FDIM];   // permuted WqkvT hi [6144][256]
__device__ __align__(16) bf16 g_Wql[(size_t)(NHEAD * FDIM * 3) * FDIM];
__device__ __align__(16) bf16 g_Wph[(size_t)FDIM * (NHEAD * FDIM)];       // WprojT hi [256][2048]
__device__ __align__(16) bf16 g_Wpl[(size_t)FDIM * (NHEAD * FDIM)];
__device__ __align__(16) bf16 g_Qh [(size_t)NBH * TLEN * FDIM];           // [bh][t][f]  (hi only)
__device__ __align__(16) bf16 g_Kh [(size_t)NBH * TLEN * FDIM];           // (hi only)
__device__ __align__(16) bf16 g_Vnh[(size_t)NBH * TLEN * FDIM];           // V natural [bh][t][f]
__device__ __align__(16) bf16 g_Vnl[(size_t)NBH * TLEN * FDIM];
__device__ __align__(16) bf16 g_Vth[(size_t)NBH * FDIM * TLEN];           // V transposed [bh][f][t]
__device__ __align__(16) bf16 g_Vtl[(size_t)NBH * FDIM * TLEN];
__device__ __align__(16) float g_S [(size_t)NBH * TLEN * TLEN];           // fp32 scores
__device__ __align__(16) bf16 g_Ph [(size_t)NBH * TLEN * TLEN];           // probs hi
__device__ __align__(16) bf16 g_Pl [(size_t)NBH * TLEN * TLEN];           // probs lo
__device__ __align__(16) bf16 g_ah [(size_t)NBATCH * TLEN * NHEAD * FDIM];// attn hi [b][t][h*f]
__device__ __align__(16) bf16 g_al [(size_t)NBATCH * TLEN * NHEAD * FDIM];

// ---------------- helpers ----------------
__device__ __forceinline__ uint32_t smem_u32(const void* p) {
    uint32_t a;
    asm("{ .reg .u64 t; cvta.to.shared.u64 t, %1; cvt.u32.u64 %0, t; }" : "=r"(a) : "l"(p));
    return a;
}
__device__ __forceinline__ void cp_async16(uint32_t dst, const void* src) {
    asm volatile("cp.async.cg.shared.global [%0], [%1], 16;" :: "r"(dst), "l"(src) : "memory");
}
__device__ __forceinline__ void cp_commit() {
    asm volatile("cp.async.commit_group;" ::: "memory");
}
template<int N> __device__ __forceinline__ void cp_wait() {
    asm volatile("cp.async.wait_group %0;" :: "n"(N) : "memory");
}
__device__ __forceinline__ void mma_bf16(float* c, const uint32_t* a, const uint32_t* b) {
    asm volatile(
        "mma.sync.aligned.m16n8k16.row.col.f32.bf16.bf16.f32 "
        "{%0,%1,%2,%3}, {%4,%5,%6,%7}, {%8,%9}, {%0,%1,%2,%3};"
        : "+f"(c[0]), "+f"(c[1]), "+f"(c[2]), "+f"(c[3])
        : "r"(a[0]), "r"(a[1]), "r"(a[2]), "r"(a[3]), "r"(b[0]), "r"(b[1]));
}
__device__ __forceinline__ uint32_t pack_hi(float lo, float hi) {
    uint32_t h;
    asm("cvt.rn.bf16x2.f32 %0, %1, %2;" : "=r"(h) : "f"(hi), "f"(lo));
    return h;
}
// split fp32 pair -> packed bf16x2 hi + bf16x2 lo residual (.x in low half)
__device__ __forceinline__ void split_pair(float2 f, uint32_t& hi, uint32_t& lo) {
    uint32_t h;
    asm("cvt.rn.bf16x2.f32 %0, %1, %2;" : "=r"(h) : "f"(f.y), "f"(f.x));
    const float h0 = __uint_as_float(h << 16);
    const float h1 = __uint_as_float(h & 0xffff0000u);
    asm("cvt.rn.bf16x2.f32 %0, %1, %2;" : "=r"(lo) : "f"(f.y - h1), "f"(f.x - h0));
    hi = h;
}
__device__ __forceinline__ void split1(float v, bf16& h, bf16& l) {
    h = __float2bfloat16(v);
    l = __float2bfloat16(v - __bfloat162float(h));
}

// ---------------- GEMM config ----------------
constexpr int BM = 128, BN = 128, BK = 32;
constexpr int SROWW = 20;                              // words/row (16 data + 4 pad): conflict-free
constexpr int TILE_WORDS = BM * SROWW;                 // 2560
constexpr int SMEM_FULL  = 2 * 4 * TILE_WORDS * 4;     // 81920 (Ah,Al,Bh,Bl x 2 stages)
constexpr int SMEM_HI    = 2 * 2 * TILE_WORDS * 4;     // 40960 (Ah,Bh x 2 stages)

// MODE 0: C[8192,6144] = x @ WqkvT'^T   (K=256)  -> Q/K hi (+bias,*1/16), V split natural
// MODE 1: C[2048,2048] = Qh @ Kh^T      (K=256)  -> g_S fp32  (hi-only, 1 MMA)
// MODE 2: C[2048, 256] = P @ Vt^T       (K=2048) -> split g_ah/g_al
// MODE 3: C[8192, 256] = attn @ WprojT^T(K=2048) -> d_out fp32 (+bias)
template<int MODE>
__global__ void __launch_bounds__(256, 2)
mma_gemm(const float* __restrict__ bias, float* __restrict__ Cgp)
{
    constexpr int NTERMS = (MODE == 1) ? 1 : 3;
    constexpr int TILES  = (NTERMS == 1) ? 2 : 4;
    constexpr int K  = (MODE == 0 || MODE == 1) ? 256 : 2048;
    constexpr int KT = K / BK;
    constexpr int STAGE_WORDS = TILES * TILE_WORDS;
    constexpr int STAGE_BYTES = STAGE_WORDS * 4;
    // tile slots: NTERMS==3: Ah=0, Al=1, Bh=2, Bl=3 ; NTERMS==1: Ah=0, Bh=1
    constexpr int SLOT_BH = (NTERMS == 1) ? 1 : 2;

    extern __shared__ uint32_t smem_w[];
    const uint32_t sbase = smem_u32(smem_w);

    const int tid = threadIdx.x;
    const int wid = tid >> 5, lid = tid & 31;
    const int z = blockIdx.z;
    const int rowBase = blockIdx.y * BM;
    const int colBase = blockIdx.x * BN;

    const bf16 *Ah, *Al = nullptr, *Bh, *Bl = nullptr;
    if (MODE == 0) {
        Ah = g_xh;  Al = g_xl;  Bh = g_Wqh; Bl = g_Wql;
    } else if (MODE == 1) {
        const size_t o = (size_t)z * TLEN * FDIM;
        Ah = g_Qh + o; Bh = g_Kh + o;
    } else if (MODE == 2) {
        const size_t oa = (size_t)z * TLEN * TLEN;
        const size_t ob = (size_t)z * FDIM * TLEN;
        Ah = g_Ph + oa; Al = g_Pl + oa; Bh = g_Vth + ob; Bl = g_Vtl + ob;
    } else {
        Ah = g_ah;  Al = g_al;  Bh = g_Wph; Bl = g_Wpl;
    }
    Ah += (size_t)rowBase * K;
    Bh += (size_t)colBase * K;
    if (NTERMS == 3) { Al += (size_t)rowBase * K; Bl += (size_t)colBase * K; }

    // loader: per tile 512 chunks of 16B; 256 threads x 2
    auto load_tile = [&](int kt, int s) {
        const uint32_t base = sbase + s * STAGE_BYTES;
        const int kofs = kt * BK;
        #pragma unroll
        for (int i = 0; i < 2; ++i) {
            const int f   = tid + 256 * i;
            const int row = f >> 2;
            const int c16 = f & 3;
            const uint32_t so = (uint32_t)(row * SROWW + c16 * 4) * 4;
            const size_t go = (size_t)row * K + kofs + c16 * 8;
            cp_async16(base + so,                              Ah + go);
            cp_async16(base + SLOT_BH * TILE_WORDS * 4 + so,   Bh + go);
            if (NTERMS == 3) {
                cp_async16(base + 1 * TILE_WORDS * 4 + so,     Al + go);
                cp_async16(base + 3 * TILE_WORDS * 4 + so,     Bl + go);
            }
        }
        cp_commit();
    };

    const int warp_m = wid & 3;   // 4 warps x 32 rows
    const int warp_n = wid >> 2;  // 2 warps x 64 cols
    const int gid = lid >> 2;     // 0..7
    const int tig = lid & 3;      // 0..3

    float acc[2][8][4];
    #pragma unroll
    for (int i = 0; i < 2; ++i)
        #pragma unroll
        for (int j = 0; j < 8; ++j)
            #pragma unroll
            for (int c = 0; c < 4; ++c) acc[i][j][c] = 0.f;

    load_tile(0, 0);

    #pragma unroll 1
    for (int kt = 0; kt < KT; ++kt) {
        const int s = kt & 1;
        if (kt + 1 < KT) { load_tile(kt + 1, s ^ 1); cp_wait<1>(); }
        else             { cp_wait<0>(); }
        __syncthreads();

        const uint32_t* st   = smem_w + s * STAGE_WORDS;
        const uint32_t* Ah_s = st + (32 * warp_m) * SROWW;
        const uint32_t* Al_s = st + 1 * TILE_WORDS + (32 * warp_m) * SROWW;
        const uint32_t* Bh_s = st + SLOT_BH * TILE_WORDS + (64 * warp_n) * SROWW;
        const uint32_t* Bl_s = st + 3 * TILE_WORDS + (64 * warp_n) * SROWW;

        #pragma unroll
        for (int ks = 0; ks < 2; ++ks) {             // two m16n8k16 K-steps per BK=32
            const int kp = ks * 8 + tig;             // bf16x2 word index along K

            uint32_t ah[2][4], al[2][4];
            #pragma unroll
            for (int i = 0; i < 2; ++i) {
                const uint32_t* p = Ah_s + (16 * i + gid) * SROWW + kp;
                ah[i][0] = p[0]; ah[i][1] = p[8 * SROWW]; ah[i][2] = p[4]; ah[i][3] = p[8 * SROWW + 4];
                if (NTERMS == 3) {
                    const uint32_t* q = Al_s + (16 * i + gid) * SROWW + kp;
                    al[i][0] = q[0]; al[i][1] = q[8 * SROWW]; al[i][2] = q[4]; al[i][3] = q[8 * SROWW + 4];
                }
            }

            #pragma unroll
            for (int jh = 0; jh < 2; ++jh) {         // halves of 4 columns (reg pressure)
                uint32_t bh[4][2], bl[4][2];
                #pragma unroll
                for (int j = 0; j < 4; ++j) {
                    const uint32_t* p = Bh_s + (8 * (jh * 4 + j) + gid) * SROWW + kp;
                    bh[j][0] = p[0]; bh[j][1] = p[4];
                    if (NTERMS == 3) {
                        const uint32_t* q = Bl_s + (8 * (jh * 4 + j) + gid) * SROWW + kp;
                        bl[j][0] = q[0]; bl[j][1] = q[4];
                    }
                }
                #pragma unroll
                for (int i = 0; i < 2; ++i)
                    #pragma unroll
                    for (int j = 0; j < 4; ++j) {
                        float* c = acc[i][jh * 4 + j];
                        mma_bf16(c, ah[i], bh[j]);           // hi*hi
                        if (NTERMS == 3) {
                            mma_bf16(c, ah[i], bl[j]);       // hi*lo
                            mma_bf16(c, al[i], bh[j]);       // lo*hi
                        }
                    }
            }
        }
        __syncthreads();
    }

    // ---------------- epilogue ----------------
    const int gm = rowBase + 32 * warp_m;
    const int gn = colBase + 64 * warp_n + 2 * tig;

    if (MODE == 0) {
        // permuted columns: jj = part*2048 + h*256 + f ; part & head uniform per CTA
        const int part  = colBase >> 11;
        const int hh    = (colBase >> 8) & 7;
        const int fwarp = (colBase & 255) + 64 * warp_n + 2 * tig;
        const float scl = (part == 2) ? 1.0f : 0.0625f;

        #pragma unroll
        for (int i = 0; i < 2; ++i) {
            #pragma unroll
            for (int h = 0; h < 2; ++h) {
                const int m = gm + 16 * i + gid + 8 * h;
                const int b = m >> 11, t = m & (TLEN - 1);
                const size_t rowO = ((size_t)(b * NHEAD + hh) * TLEN + t) * FDIM;
                #pragma unroll
                for (int j = 0; j < 8; ++j) {
                    const int f0 = fwarp + 8 * j;
                    const int borig = hh * (FDIM * 3) + f0 * 3 + part;
                    float v0 = (acc[i][j][2 * h]     + bias[borig])     * scl;
                    float v1 = (acc[i][j][2 * h + 1] + bias[borig + 3]) * scl;
                    if (part == 0) {
                        *(uint32_t*)(g_Qh + rowO + f0) = pack_hi(v0, v1);
                    } else if (part == 1) {
                        *(uint32_t*)(g_Kh + rowO + f0) = pack_hi(v0, v1);
                    } else {
                        uint32_t hw, lw;
                        split_pair(make_float2(v0, v1), hw, lw);
                        *(uint32_t*)(g_Vnh + rowO + f0) = hw;
                        *(uint32_t*)(g_Vnl + rowO + f0) = lw;
                    }
                }
            }
        }
        return;
    }

    #pragma unroll
    for (int i = 0; i < 2; ++i) {
        #pragma unroll
        for (int h = 0; h < 2; ++h) {
            const int m = gm + 16 * i + gid + 8 * h;

            if (MODE == 1) {
                float* p = g_S + (size_t)z * TLEN * TLEN + (size_t)m * TLEN + gn;
                #pragma unroll
                for (int j = 0; j < 8; ++j)
                    *(float2*)(p + 8 * j) = make_float2(acc[i][j][2 * h], acc[i][j][2 * h + 1]);
            } else if (MODE == 2) {
                const int b = z >> 3, hh = z & 7;
                const size_t base = ((size_t)(b * TLEN + m)) * (NHEAD * FDIM) + hh * FDIM + gn;
                #pragma unroll
                for (int j = 0; j < 8; ++j) {
                    uint32_t hw, lw;
                    split_pair(make_float2(acc[i][j][2 * h], acc[i][j][2 * h + 1]), hw, lw);
                    *(uint32_t*)(g_ah + base + 8 * j) = hw;
                    *(uint32_t*)(g_al + base + 8 * j) = lw;
                }
            } else {
                float* p = Cgp + (size_t)m * FDIM + gn;
                #pragma unroll
                for (int j = 0; j < 8; ++j)
                    *(float2*)(p + 8 * j) = make_float2(acc[i][j][2 * h]     + bias[gn + 8 * j],
                                                        acc[i][j][2 * h + 1] + bias[gn + 8 * j + 1]);
            }
        }
    }
}

// ---------------- input split: x -> g_xh/g_xl ----------------
__global__ void __launch_bounds__(256) split_x_kernel(const float* __restrict__ x)
{
    const size_t i = ((size_t)blockIdx.x * 256 + threadIdx.x) * 4;
    const float4 v = *(const float4*)(x + i);
    uint32_t h0, l0, h1, l1;
    split_pair(make_float2(v.x, v.y), h0, l0);
    split_pair(make_float2(v.z, v.w), h1, l1);
    *(uint32_t*)(g_xh + i)     = h0;
    *(uint32_t*)(g_xh + i + 2) = h1;
    *(uint32_t*)(g_xl + i)     = l0;
    *(uint32_t*)(g_xl + i + 2) = l1;
}

// ---------------- W_qkv transpose + column permutation + split ----------------
// in:  W_qkv [256][6144], col_orig = h*768 + f*3 + part
// out: g_Wqh/g_Wql [6144][256], row (col_new) = part*2048 + h*256 + f
__global__ void __launch_bounds__(256) wqkv_prep_kernel(const float* __restrict__ in)
{
    __shared__ float t[32][33];
    const int c0 = blockIdx.x * 32;
    const int r0 = blockIdx.y * 32;
    const int tx = threadIdx.x, ty = threadIdx.y;
    #pragma unroll
    for (int i = 0; i < 32; i += 8)
        t[ty + i][tx] = in[(size_t)(r0 + ty + i) * (NHEAD * FDIM * 3) + c0 + tx];
    __syncthreads();
    #pragma unroll
    for (int i = 0; i < 32; i += 8) {
        const int corig = c0 + ty + i;
        const int hh  = corig / (FDIM * 3);
        const int rem = corig - hh * (FDIM * 3);
        const int f   = rem / 3;
        const int prt = rem - f * 3;
        const int cnew = prt * (NHEAD * FDIM) + hh * FDIM + f;
        bf16 vh, vl;
        split1(t[tx][ty + i], vh, vl);
        g_Wqh[(size_t)cnew * FDIM + r0 + tx] = vh;
        g_Wql[(size_t)cnew * FDIM + r0 + tx] = vl;
    }
}

// ---------------- W_proj transpose + split: [2048][256] -> [256][2048] ----------------
__global__ void __launch_bounds__(256) wproj_prep_kernel(const float* __restrict__ in)
{
    __shared__ float t[32][33];
    const int c0 = blockIdx.x * 32;   // cols of in (256)
    const int r0 = blockIdx.y * 32;   // rows of in (2048)
    const int tx = threadIdx.x, ty = threadIdx.y;
    #pragma unroll
    for (int i = 0; i < 32; i += 8)
        t[ty + i][tx] = in[(size_t)(r0 + ty + i) * FDIM + c0 + tx];
    __syncthreads();
    #pragma unroll
    for (int i = 0; i < 32; i += 8) {
        bf16 vh, vl;
        split1(t[tx][ty + i], vh, vl);
        g_Wph[(size_t)(c0 + ty + i) * (NHEAD * FDIM) + r0 + tx] = vh;
        g_Wpl[(size_t)(c0 + ty + i) * (NHEAD * FDIM) + r0 + tx] = vl;
    }
}

// ---------------- V transpose: [bh][t][f] -> [bh][f][t] (hi & lo) ----------------
__global__ void __launch_bounds__(256) vtrans_kernel()
{
    __shared__ bf16 th[32][33], tl[32][33];
    const int bh = blockIdx.z;
    const int f0 = blockIdx.x * 32;
    const int t0 = blockIdx.y * 32;
    const int tx = threadIdx.x, ty = threadIdx.y;
    const size_t inb = ((size_t)bh * TLEN + t0) * FDIM + f0;
    #pragma unroll
    for (int i = 0; i < 32; i += 8) {
        th[ty + i][tx] = g_Vnh[inb + (size_t)(ty + i) * FDIM + tx];
        tl[ty + i][tx] = g_Vnl[inb + (size_t)(ty + i) * FDIM + tx];
    }
    __syncthreads();
    const size_t outb = ((size_t)bh * FDIM + f0) * TLEN + t0;
    #pragma unroll
    for (int i = 0; i < 32; i += 8) {
        g_Vth[outb + (size_t)(ty + i) * TLEN + tx] = th[tx][ty + i];
        g_Vtl[outb + (size_t)(ty + i) * TLEN + tx] = tl[tx][ty + i];
    }
}

// ---------------- softmax: 65536 rows of 2048; write split bf16 probs ----------------
__global__ void __launch_bounds__(256) softmax_kernel()
{
    const size_t row = blockIdx.x;
    const float* p = g_S + row * (size_t)TLEN;
    const int t = threadIdx.x;

    float4 v0 = ((const float4*)p)[t];
    float4 v1 = ((const float4*)p)[t + 256];

    float m = fmaxf(fmaxf(fmaxf(v0.x, v0.y), fmaxf(v0.z, v0.w)),
                    fmaxf(fmaxf(v1.x, v1.y), fmaxf(v1.z, v1.w)));
    #pragma unroll
    for (int o = 16; o; o >>= 1) m = fmaxf(m, __shfl_xor_sync(0xffffffffu, m, o));

    __shared__ float red[8];
    const int warp = t >> 5, lane = t & 31;
    if (lane == 0) red[warp] = m;
    __syncthreads();
    float bm = red[0];
    #pragma unroll
    for (int i = 1; i < 8; ++i) bm = fmaxf(bm, red[i]);
    __syncthreads();

    v0.x = __expf(v0.x - bm); v0.y = __expf(v0.y - bm);
    v0.z = __expf(v0.z - bm); v0.w = __expf(v0.w - bm);
    v1.x = __expf(v1.x - bm); v1.y = __expf(v1.y - bm);
    v1.z = __expf(v1.z - bm); v1.w = __expf(v1.w - bm);

    float s = v0.x + v0.y + v0.z + v0.w + v1.x + v1.y + v1.z + v1.w;
    #pragma unroll
    for (int o = 16; o; o >>= 1) s += __shfl_xor_sync(0xffffffffu, s, o);
    if (lane == 0) red[warp] = s;
    __syncthreads();
    float bs = 0.f;
    #pragma unroll
    for (int i = 0; i < 8; ++i) bs += red[i];

    const float inv = 1.0f / bs;
    v0.x *= inv; v0.y *= inv; v0.z *= inv; v0.w *= inv;
    v1.x *= inv; v1.y *= inv; v1.z *= inv; v1.w *= inv;

    uint32_t* ph = (uint32_t*)(g_Ph + row * (size_t)TLEN);
    uint32_t* pl = (uint32_t*)(g_Pl + row * (size_t)TLEN);
    uint32_t hw, lw;
    split_pair(make_float2(v0.x, v0.y), hw, lw); ph[2 * t]       = hw; pl[2 * t]       = lw;
    split_pair(make_float2(v0.z, v0.w), hw, lw); ph[2 * t + 1]   = hw; pl[2 * t + 1]   = lw;
    split_pair(make_float2(v1.x, v1.y), hw, lw); ph[2 * t + 512] = hw; pl[2 * t + 512] = lw;
    split_pair(make_float2(v1.z, v1.w), hw, lw); ph[2 * t + 513] = hw; pl[2 * t + 513] = lw;
}

// ---------------- launch ----------------
extern "C" void kernel_launch(void* const* d_in, const int* in_sizes, int n_in,
                              void* d_out, int out_size)
{
    const float* x     = (const float*)d_in[0];
    const float* Wqkv  = (const float*)d_in[1];
    const float* bqkv  = (const float*)d_in[2];
    const float* Wproj = (const float*)d_in[3];
    const float* bproj = (const float*)d_in[4];
    float* out = (float*)d_out;

    cudaFuncSetAttribute(mma_gemm<0>, cudaFuncAttributeMaxDynamicSharedMemorySize, SMEM_FULL);
    cudaFuncSetAttribute(mma_gemm<1>, cudaFuncAttributeMaxDynamicSharedMemorySize, SMEM_HI);
    cudaFuncSetAttribute(mma_gemm<2>, cudaFuncAttributeMaxDynamicSharedMemorySize, SMEM_FULL);
    cudaFuncSetAttribute(mma_gemm<3>, cudaFuncAttributeMaxDynamicSharedMemorySize, SMEM_FULL);

    // prep: split x; transpose(+permute)+split weights
    split_x_kernel<<<(NBATCH * TLEN * FDIM) / 1024, 256>>>(x);
    wqkv_prep_kernel<<<dim3(6144 / 32, 256 / 32), dim3(32, 8)>>>(Wqkv);
    wproj_prep_kernel<<<dim3(256 / 32, 2048 / 32), dim3(32, 8)>>>(Wproj);

    // 1) QKV GEMM (+bias, scale) -> Qh/Kh hi, V split natural
    mma_gemm<0><<<dim3(6144 / BN, 8192 / BM, 1), 256, SMEM_FULL>>>(bqkv, nullptr);
    // 1b) V transpose -> Vth/Vtl
    vtrans_kernel<<<dim3(FDIM / 32, TLEN / 32, NBH), dim3(32, 8)>>>();
    // 2) scores = Qh Kh^T (hi-only, batched over 32 bh) -> fp32 S
    mma_gemm<1><<<dim3(TLEN / BN, TLEN / BM, NBH), 256, SMEM_HI>>>(nullptr, nullptr);
    // 3) softmax -> split bf16 P
    softmax_kernel<<<NBH * TLEN, 256>>>();
    // 4) out = P V (batched, NT against Vt) -> split bf16 attn
    mma_gemm<2><<<dim3(FDIM / BN, TLEN / BM, NBH), 256, SMEM_FULL>>>(nullptr, nullptr);
    // 5) proj (+bias) -> fp32 out
    mma_gemm<3><<<dim3(FDIM / BN, 8192 / BM, 1), 256, SMEM_FULL>>>(bproj, out);
}